// round 4
// baseline (speedup 1.0000x reference)
#include <cuda_runtime.h>
#include <cuda_bf16.h>

// BoxDecoder: anchor decode + score-threshold mask.
// out layout (f32): [ box_tensor (B*A*C*6) | mask (B*A*C) | batch_index (B*A*C) ]
//
// R4: unpadded smem staging (ROW=48) == output layout, so the copy-out phase
// is a pure linear float4 stream (no div/mod). STS.128 at 48-float stride is
// bank-conflict-free (12*l mod 32 distinct over 8-lane phases). Plain stores
// (the .cs hints of R3 regressed). Warp-autonomous: __syncwarp only.

constexpr int TPB = 128;          // 4 warps per block
constexpr int ROW = 48;           // smem row stride == output row group (8 rows * 6 f)

__global__ void __launch_bounds__(TPB)
box_decode_c8_kernel(const float* __restrict__ anchors,   // [A,4] cx,cy,w,h
                     const float* __restrict__ loc,       // [B,A,4]
                     const float* __restrict__ cls,       // [B,A,8]
                     const float* __restrict__ varx_p,
                     const float* __restrict__ vary_p,
                     const float* __restrict__ thr_p,
                     float* __restrict__ out_box,         // [B*A*8, 6]
                     float* __restrict__ out_mask,        // [B*A*8] or null
                     float* __restrict__ out_bidx,        // [B*A*8] or null
                     int A, long long total)              // total = B*A
{
    __shared__ float sm[TPB * ROW];

    const long long bs = (long long)blockIdx.x * TPB;   // first t of this block
    const int tid  = threadIdx.x;
    const int w    = tid >> 5;                           // warp id in block
    const int lane = tid & 31;
    const long long t = bs + tid;

    const float varx = *varx_p;
    const float vary = *vary_p;
    const float thr  = *thr_p;

    // ---- mask: elementwise over cls float4s, coalesced ----
    if (out_mask) {
#pragma unroll
        for (int k = 0; k < 2; k++) {
            long long j = bs * 2 + (long long)k * TPB + tid;
            if (j < total * 2) {
                float4 sv = __ldg((const float4*)cls + j);
                ((float4*)out_mask)[j] = make_float4(
                    sv.x >= thr ? 1.0f : 0.0f,
                    sv.y >= thr ? 1.0f : 0.0f,
                    sv.z >= thr ? 1.0f : 0.0f,
                    sv.w >= thr ? 1.0f : 0.0f);
            }
        }
    }

    // ---- batch_index: derived from index, coalesced ----
    if (out_bidx) {
#pragma unroll
        for (int k = 0; k < 2; k++) {
            long long j = bs * 2 + (long long)k * TPB + tid;  // float4 idx, t = j/2
            if (j < total * 2) {
                float bf = (float)(int)((j >> 1) / A);
                ((float4*)out_bidx)[j] = make_float4(bf, bf, bf, bf);
            }
        }
    }

    // ---- phase 1: decode own t, stage 48 floats into smem (output layout) ----
    if (t < total) {
        int a = (int)(t % A);

        float4 anc = __ldg((const float4*)anchors + a);   // cx,cy,w,h
        float4 lp  = __ldg((const float4*)loc + t);

        float cx = lp.x * varx * anc.z + anc.x;
        float cy = lp.y * varx * anc.w + anc.y;
        float wd = __expf(lp.z * vary) * anc.z;
        float ht = __expf(lp.w * vary) * anc.w;

        float x0 = cx - 0.5f * wd;
        float y0 = cy - 0.5f * ht;
        float x1 = cx + 0.5f * wd;
        float y1 = cy + 0.5f * ht;

        float4 s01 = __ldg((const float4*)cls + t * 2);
        float4 s23 = __ldg((const float4*)cls + t * 2 + 1);
        float s[8] = { s01.x, s01.y, s01.z, s01.w, s23.x, s23.y, s23.z, s23.w };

        float4* row = (float4*)(sm + tid * ROW);   // 192B stride, conflict-free
#pragma unroll
        for (int p = 0; p < 4; p++) {              // class pair (2p, 2p+1)
            row[3 * p + 0] = make_float4(x0, y0, x1, y1);
            row[3 * p + 1] = make_float4(s[2 * p], (float)(2 * p + 1), x0, y0);
            row[3 * p + 2] = make_float4(x1, y1, s[2 * p + 1], (float)(2 * p + 2));
        }
    }
    __syncwarp();

    // ---- phase 2: linear smem -> gmem copy, fully coalesced ----
    {
        const long long wbase = bs + (long long)w * 32;           // first t of warp
        const int nf4 = (int)max(0LL, min(32LL, total - wbase)) * 12;
        float4* dst = (float4*)out_box + wbase * 12;
        const float4* src = (const float4*)(sm + (w * 32) * ROW); // linear!
#pragma unroll
        for (int k = 0; k < 12; k++) {
            int i = lane + k * 32;                  // 0..383
            if (i < nf4) dst[i] = src[i];
        }
    }
}

// Generic-C fallback (scalar stores), in case C != 8.
__global__ void __launch_bounds__(256)
box_decode_generic_kernel(const float* __restrict__ anchors,
                          const float* __restrict__ loc,
                          const float* __restrict__ cls,
                          const float* __restrict__ varx_p,
                          const float* __restrict__ vary_p,
                          const float* __restrict__ thr_p,
                          float* __restrict__ out_box,
                          float* __restrict__ out_mask,
                          float* __restrict__ out_bidx,
                          int A, int C, long long total)
{
    long long t = (long long)blockIdx.x * blockDim.x + threadIdx.x;
    if (t >= total) return;

    const float varx = *varx_p;
    const float vary = *vary_p;
    const float thr  = *thr_p;

    int b = (int)(t / A);
    int a = (int)(t - (long long)b * A);

    float4 anc = __ldg((const float4*)anchors + a);
    float4 lp  = __ldg((const float4*)loc + t);

    float cx = lp.x * varx * anc.z + anc.x;
    float cy = lp.y * varx * anc.w + anc.y;
    float w  = expf(lp.z * vary) * anc.z;
    float h  = expf(lp.w * vary) * anc.w;

    float x0 = cx - 0.5f * w;
    float y0 = cy - 0.5f * h;
    float x1 = cx + 0.5f * w;
    float y1 = cy + 0.5f * h;

    for (int c = 0; c < C; c++) {
        long long r = t * C + c;
        float sc = cls[r];
        float* row = out_box + r * 6;
        row[0] = x0; row[1] = y0; row[2] = x1; row[3] = y1;
        row[4] = sc; row[5] = (float)(c + 1);
        if (out_mask) out_mask[r] = (sc >= thr) ? 1.0f : 0.0f;
        if (out_bidx) out_bidx[r] = (float)b;
    }
}

extern "C" void kernel_launch(void* const* d_in, const int* in_sizes, int n_in,
                              void* d_out, int out_size)
{
    // Input order per setup_inputs: anchors, loc_preds, cls_preds,
    // varx, vary, score_thresh, batch_size
    const float* anchors = (const float*)d_in[0];
    const float* loc     = (const float*)d_in[1];
    const float* cls     = (const float*)d_in[2];
    const float* varx_p  = (const float*)d_in[3];
    const float* vary_p  = (const float*)d_in[4];
    const float* thr_p   = (const float*)d_in[5];

    const long long A   = in_sizes[0] / 4;
    const long long B   = in_sizes[1] / (A * 4);
    const long long C   = in_sizes[2] / (B * A);
    const long long BAC = B * A * C;
    const long long total = B * A;

    float* out = (float*)d_out;
    float* out_box  = out;                                        // BAC*6
    float* out_mask = (out_size >= (long long)(BAC * 7)) ? out + BAC * 6 : nullptr;
    float* out_bidx = (out_size >= (long long)(BAC * 8)) ? out + BAC * 7 : nullptr;

    // Hedge: if the harness allocated more than we write, clear the tail
    // (d_out is poisoned to 0xAA). Graph-capturable async memset.
    long long written = BAC * 6;
    if (out_mask) written = BAC * 7;
    if (out_bidx) written = BAC * 8;
    if ((long long)out_size > written) {
        cudaMemsetAsync(out + written, 0,
                        ((long long)out_size - written) * sizeof(float));
    }

    if (C == 8) {
        const long long blocks = (total + TPB - 1) / TPB;
        box_decode_c8_kernel<<<(unsigned)blocks, TPB>>>(
            anchors, loc, cls, varx_p, vary_p, thr_p,
            out_box, out_mask, out_bidx, (int)A, total);
    } else {
        const int threads = 256;
        const long long blocks = (total + threads - 1) / threads;
        box_decode_generic_kernel<<<(unsigned)blocks, threads>>>(
            anchors, loc, cls, varx_p, vary_p, thr_p,
            out_box, out_mask, out_bidx, (int)A, (int)C, total);
    }
}

// round 6
// speedup vs baseline: 1.1207x; 1.1207x over previous
#include <cuda_runtime.h>
#include <cuda_bf16.h>

// BoxDecoder: anchor decode + score-threshold mask.
// out layout (f32): [ box_tensor (B*A*C*6) | mask (B*A*C) | batch_index (B*A*C) ]
//
// R6 = R2 structure (padded smem staging ROW=52, block-phased flush, plain
// stores) but with SPLIT-TILE staging: decode all 128 t's into registers,
// then stage+flush in two rounds of 64 t's through a half-size smem buffer
// (13.3KB). smem no longer binds occupancy (regs do: ~9 blocks/SM, 36 warps
// vs R2's 8 blocks/32 warps).
// NOTE: ROW must be mult of 4 (float4 align) and ROW mod 32 in {4,12,20,28}
// (conflict-free STS.128) -> 52 is minimal. R5's ROW=49 trapped on alignment.

constexpr int TPB  = 128;         // 4 warps per block
constexpr int HALF = 64;          // t's staged per round
constexpr int ROW  = 52;          // padded smem row stride (48 data + 4 pad)

__global__ void __launch_bounds__(TPB)
box_decode_c8_kernel(const float* __restrict__ anchors,   // [A,4] cx,cy,w,h
                     const float* __restrict__ loc,       // [B,A,4]
                     const float* __restrict__ cls,       // [B,A,8]
                     const float* __restrict__ varx_p,
                     const float* __restrict__ vary_p,
                     const float* __restrict__ thr_p,
                     float* __restrict__ out_box,         // [B*A*8, 6]
                     float* __restrict__ out_mask,        // [B*A*8] or null
                     float* __restrict__ out_bidx,        // [B*A*8] or null
                     int A, long long total)              // total = B*A
{
    __shared__ float sm[HALF * ROW];

    const long long bs = (long long)blockIdx.x * TPB;   // first t of this block
    const int tid = threadIdx.x;
    const long long t = bs + tid;

    const float varx = *varx_p;
    const float vary = *vary_p;
    const float thr  = *thr_p;

    // ---- mask: elementwise over cls float4s, perfectly coalesced ----
    if (out_mask) {
#pragma unroll
        for (int k = 0; k < 2; k++) {
            long long j = bs * 2 + (long long)k * TPB + tid;
            if (j < total * 2) {
                float4 sv = __ldg((const float4*)cls + j);
                ((float4*)out_mask)[j] = make_float4(
                    sv.x >= thr ? 1.0f : 0.0f,
                    sv.y >= thr ? 1.0f : 0.0f,
                    sv.z >= thr ? 1.0f : 0.0f,
                    sv.w >= thr ? 1.0f : 0.0f);
            }
        }
    }

    // ---- batch_index: derived from index, coalesced ----
    if (out_bidx) {
#pragma unroll
        for (int k = 0; k < 2; k++) {
            long long j = bs * 2 + (long long)k * TPB + tid;  // float4 idx, t = j/2
            if (j < total * 2) {
                float bf = (float)(int)((j >> 1) / A);
                ((float4*)out_bidx)[j] = make_float4(bf, bf, bf, bf);
            }
        }
    }

    // ---- decode own t into registers ----
    float x0 = 0.f, y0 = 0.f, x1 = 0.f, y1 = 0.f;
    float s[8] = {0.f, 0.f, 0.f, 0.f, 0.f, 0.f, 0.f, 0.f};
    if (t < total) {
        int a = (int)(t % A);

        float4 anc = __ldg((const float4*)anchors + a);   // cx,cy,w,h
        float4 lp  = __ldg((const float4*)loc + t);

        float cx = lp.x * varx * anc.z + anc.x;
        float cy = lp.y * varx * anc.w + anc.y;
        float wd = __expf(lp.z * vary) * anc.z;
        float ht = __expf(lp.w * vary) * anc.w;

        x0 = cx - 0.5f * wd;
        y0 = cy - 0.5f * ht;
        x1 = cx + 0.5f * wd;
        y1 = cy + 0.5f * ht;

        float4 s01 = __ldg((const float4*)cls + t * 2);
        float4 s23 = __ldg((const float4*)cls + t * 2 + 1);
        s[0] = s01.x; s[1] = s01.y; s[2] = s01.z; s[3] = s01.w;
        s[4] = s23.x; s[5] = s23.y; s[6] = s23.z; s[7] = s23.w;
    }

    // ---- two rounds: stage HALF t's, flush coalesced ----
#pragma unroll
    for (int round = 0; round < 2; round++) {
        if ((tid >> 6) == round && t < total) {
            float4* row = (float4*)(sm + (tid & (HALF - 1)) * ROW);
#pragma unroll
            for (int p = 0; p < 4; p++) {          // class pair (2p, 2p+1)
                row[3 * p + 0] = make_float4(x0, y0, x1, y1);
                row[3 * p + 1] = make_float4(s[2 * p], (float)(2 * p + 1), x0, y0);
                row[3 * p + 2] = make_float4(x1, y1, s[2 * p + 1], (float)(2 * p + 2));
            }
        }
        __syncthreads();

        const long long rbase = bs + (long long)round * HALF;     // first t this round
        const int nvalid = (int)max(0LL, min((long long)HALF, total - rbase));
        const int nf4 = nvalid * 12;
        float4* dst = (float4*)out_box + rbase * 12;
#pragma unroll
        for (int k = 0; k < 6; k++) {              // HALF*12 / TPB = 6
            int i = tid + k * TPB;
            if (i < nf4) {
                int tl  = i / 12;
                int pos = i - tl * 12;
                dst[i] = *(const float4*)(sm + tl * ROW + pos * 4);
            }
        }
        if (round == 0) __syncthreads();           // protect buffer before reuse
    }
}

// Generic-C fallback (scalar stores), in case C != 8.
__global__ void __launch_bounds__(256)
box_decode_generic_kernel(const float* __restrict__ anchors,
                          const float* __restrict__ loc,
                          const float* __restrict__ cls,
                          const float* __restrict__ varx_p,
                          const float* __restrict__ vary_p,
                          const float* __restrict__ thr_p,
                          float* __restrict__ out_box,
                          float* __restrict__ out_mask,
                          float* __restrict__ out_bidx,
                          int A, int C, long long total)
{
    long long t = (long long)blockIdx.x * blockDim.x + threadIdx.x;
    if (t >= total) return;

    const float varx = *varx_p;
    const float vary = *vary_p;
    const float thr  = *thr_p;

    int b = (int)(t / A);
    int a = (int)(t - (long long)b * A);

    float4 anc = __ldg((const float4*)anchors + a);
    float4 lp  = __ldg((const float4*)loc + t);

    float cx = lp.x * varx * anc.z + anc.x;
    float cy = lp.y * varx * anc.w + anc.y;
    float w  = expf(lp.z * vary) * anc.z;
    float h  = expf(lp.w * vary) * anc.w;

    float x0 = cx - 0.5f * w;
    float y0 = cy - 0.5f * h;
    float x1 = cx + 0.5f * w;
    float y1 = cy + 0.5f * h;

    for (int c = 0; c < C; c++) {
        long long r = t * C + c;
        float sc = cls[r];
        float* row = out_box + r * 6;
        row[0] = x0; row[1] = y0; row[2] = x1; row[3] = y1;
        row[4] = sc; row[5] = (float)(c + 1);
        if (out_mask) out_mask[r] = (sc >= thr) ? 1.0f : 0.0f;
        if (out_bidx) out_bidx[r] = (float)b;
    }
}

extern "C" void kernel_launch(void* const* d_in, const int* in_sizes, int n_in,
                              void* d_out, int out_size)
{
    // Input order per setup_inputs: anchors, loc_preds, cls_preds,
    // varx, vary, score_thresh, batch_size
    const float* anchors = (const float*)d_in[0];
    const float* loc     = (const float*)d_in[1];
    const float* cls     = (const float*)d_in[2];
    const float* varx_p  = (const float*)d_in[3];
    const float* vary_p  = (const float*)d_in[4];
    const float* thr_p   = (const float*)d_in[5];

    const long long A   = in_sizes[0] / 4;
    const long long B   = in_sizes[1] / (A * 4);
    const long long C   = in_sizes[2] / (B * A);
    const long long BAC = B * A * C;
    const long long total = B * A;

    float* out = (float*)d_out;
    float* out_box  = out;                                        // BAC*6
    float* out_mask = (out_size >= (long long)(BAC * 7)) ? out + BAC * 6 : nullptr;
    float* out_bidx = (out_size >= (long long)(BAC * 8)) ? out + BAC * 7 : nullptr;

    // Hedge: if the harness allocated more than we write, clear the tail
    // (d_out is poisoned to 0xAA). Graph-capturable async memset.
    long long written = BAC * 6;
    if (out_mask) written = BAC * 7;
    if (out_bidx) written = BAC * 8;
    if ((long long)out_size > written) {
        cudaMemsetAsync(out + written, 0,
                        ((long long)out_size - written) * sizeof(float));
    }

    if (C == 8) {
        const long long blocks = (total + TPB - 1) / TPB;
        box_decode_c8_kernel<<<(unsigned)blocks, TPB>>>(
            anchors, loc, cls, varx_p, vary_p, thr_p,
            out_box, out_mask, out_bidx, (int)A, total);
    } else {
        const int threads = 256;
        const long long blocks = (total + threads - 1) / threads;
        box_decode_generic_kernel<<<(unsigned)blocks, threads>>>(
            anchors, loc, cls, varx_p, vary_p, thr_p,
            out_box, out_mask, out_bidx, (int)A, (int)C, total);
    }
}

// round 7
// speedup vs baseline: 1.1212x; 1.0004x over previous
#include <cuda_runtime.h>
#include <cuda_bf16.h>

// BoxDecoder: anchor decode + score-threshold mask.
// out layout (f32): [ box_tensor (B*A*C*6) | mask (B*A*C) | batch_index (B*A*C) ]
//
// R7 = R6 with QUARTER-buffer staging: decode all 128 t's into registers,
// then stage+flush in FOUR rounds of 32 t's through a 6.65KB smem buffer.
// smem no longer limits occupancy at all (16 blocks/SM = 64 warps needs only
// 106KB); regs=34 -> reg/warp-limited at full occupancy.
// ROW=52: mult-of-4 (float4 align) + ROW mod 32 == 20 -> conflict-free STS.128.

constexpr int TPB    = 128;       // 4 warps per block
constexpr int STAGE  = 32;        // t's staged per round
constexpr int ROUNDS = TPB / STAGE;
constexpr int ROW    = 52;        // padded smem row stride (48 data + 4 pad)

__global__ void __launch_bounds__(TPB)
box_decode_c8_kernel(const float* __restrict__ anchors,   // [A,4] cx,cy,w,h
                     const float* __restrict__ loc,       // [B,A,4]
                     const float* __restrict__ cls,       // [B,A,8]
                     const float* __restrict__ varx_p,
                     const float* __restrict__ vary_p,
                     const float* __restrict__ thr_p,
                     float* __restrict__ out_box,         // [B*A*8, 6]
                     float* __restrict__ out_mask,        // [B*A*8] or null
                     float* __restrict__ out_bidx,        // [B*A*8] or null
                     int A, long long total)              // total = B*A
{
    __shared__ float sm[STAGE * ROW];

    const long long bs = (long long)blockIdx.x * TPB;   // first t of this block
    const int tid = threadIdx.x;
    const long long t = bs + tid;

    const float varx = *varx_p;
    const float vary = *vary_p;
    const float thr  = *thr_p;

    // ---- mask: elementwise over cls float4s, perfectly coalesced ----
    if (out_mask) {
#pragma unroll
        for (int k = 0; k < 2; k++) {
            long long j = bs * 2 + (long long)k * TPB + tid;
            if (j < total * 2) {
                float4 sv = __ldg((const float4*)cls + j);
                ((float4*)out_mask)[j] = make_float4(
                    sv.x >= thr ? 1.0f : 0.0f,
                    sv.y >= thr ? 1.0f : 0.0f,
                    sv.z >= thr ? 1.0f : 0.0f,
                    sv.w >= thr ? 1.0f : 0.0f);
            }
        }
    }

    // ---- batch_index: derived from index, coalesced ----
    if (out_bidx) {
#pragma unroll
        for (int k = 0; k < 2; k++) {
            long long j = bs * 2 + (long long)k * TPB + tid;  // float4 idx, t = j/2
            if (j < total * 2) {
                float bf = (float)(int)((j >> 1) / A);
                ((float4*)out_bidx)[j] = make_float4(bf, bf, bf, bf);
            }
        }
    }

    // ---- decode own t into registers ----
    float x0 = 0.f, y0 = 0.f, x1 = 0.f, y1 = 0.f;
    float s[8] = {0.f, 0.f, 0.f, 0.f, 0.f, 0.f, 0.f, 0.f};
    if (t < total) {
        int a = (int)(t % A);

        float4 anc = __ldg((const float4*)anchors + a);   // cx,cy,w,h
        float4 lp  = __ldg((const float4*)loc + t);

        float cx = lp.x * varx * anc.z + anc.x;
        float cy = lp.y * varx * anc.w + anc.y;
        float wd = __expf(lp.z * vary) * anc.z;
        float ht = __expf(lp.w * vary) * anc.w;

        x0 = cx - 0.5f * wd;
        y0 = cy - 0.5f * ht;
        x1 = cx + 0.5f * wd;
        y1 = cy + 0.5f * ht;

        float4 s01 = __ldg((const float4*)cls + t * 2);
        float4 s23 = __ldg((const float4*)cls + t * 2 + 1);
        s[0] = s01.x; s[1] = s01.y; s[2] = s01.z; s[3] = s01.w;
        s[4] = s23.x; s[5] = s23.y; s[6] = s23.z; s[7] = s23.w;
    }

    // ---- ROUNDS rounds: stage STAGE t's, flush coalesced ----
#pragma unroll
    for (int round = 0; round < ROUNDS; round++) {
        if ((tid >> 5) == round && t < total) {
            float4* row = (float4*)(sm + (tid & (STAGE - 1)) * ROW);
#pragma unroll
            for (int p = 0; p < 4; p++) {          // class pair (2p, 2p+1)
                row[3 * p + 0] = make_float4(x0, y0, x1, y1);
                row[3 * p + 1] = make_float4(s[2 * p], (float)(2 * p + 1), x0, y0);
                row[3 * p + 2] = make_float4(x1, y1, s[2 * p + 1], (float)(2 * p + 2));
            }
        }
        __syncthreads();

        const long long rbase = bs + (long long)round * STAGE;    // first t this round
        const int nvalid = (int)max(0LL, min((long long)STAGE, total - rbase));
        const int nf4 = nvalid * 12;
        float4* dst = (float4*)out_box + rbase * 12;
#pragma unroll
        for (int k = 0; k < 3; k++) {              // STAGE*12 / TPB = 3
            int i = tid + k * TPB;
            if (i < nf4) {
                int tl  = i / 12;
                int pos = i - tl * 12;
                dst[i] = *(const float4*)(sm + tl * ROW + pos * 4);
            }
        }
        if (round != ROUNDS - 1) __syncthreads();  // protect buffer before reuse
    }
}

// Generic-C fallback (scalar stores), in case C != 8.
__global__ void __launch_bounds__(256)
box_decode_generic_kernel(const float* __restrict__ anchors,
                          const float* __restrict__ loc,
                          const float* __restrict__ cls,
                          const float* __restrict__ varx_p,
                          const float* __restrict__ vary_p,
                          const float* __restrict__ thr_p,
                          float* __restrict__ out_box,
                          float* __restrict__ out_mask,
                          float* __restrict__ out_bidx,
                          int A, int C, long long total)
{
    long long t = (long long)blockIdx.x * blockDim.x + threadIdx.x;
    if (t >= total) return;

    const float varx = *varx_p;
    const float vary = *vary_p;
    const float thr  = *thr_p;

    int b = (int)(t / A);
    int a = (int)(t - (long long)b * A);

    float4 anc = __ldg((const float4*)anchors + a);
    float4 lp  = __ldg((const float4*)loc + t);

    float cx = lp.x * varx * anc.z + anc.x;
    float cy = lp.y * varx * anc.w + anc.y;
    float w  = expf(lp.z * vary) * anc.z;
    float h  = expf(lp.w * vary) * anc.w;

    float x0 = cx - 0.5f * w;
    float y0 = cy - 0.5f * h;
    float x1 = cx + 0.5f * w;
    float y1 = cy + 0.5f * h;

    for (int c = 0; c < C; c++) {
        long long r = t * C + c;
        float sc = cls[r];
        float* row = out_box + r * 6;
        row[0] = x0; row[1] = y0; row[2] = x1; row[3] = y1;
        row[4] = sc; row[5] = (float)(c + 1);
        if (out_mask) out_mask[r] = (sc >= thr) ? 1.0f : 0.0f;
        if (out_bidx) out_bidx[r] = (float)b;
    }
}

extern "C" void kernel_launch(void* const* d_in, const int* in_sizes, int n_in,
                              void* d_out, int out_size)
{
    // Input order per setup_inputs: anchors, loc_preds, cls_preds,
    // varx, vary, score_thresh, batch_size
    const float* anchors = (const float*)d_in[0];
    const float* loc     = (const float*)d_in[1];
    const float* cls     = (const float*)d_in[2];
    const float* varx_p  = (const float*)d_in[3];
    const float* vary_p  = (const float*)d_in[4];
    const float* thr_p   = (const float*)d_in[5];

    const long long A   = in_sizes[0] / 4;
    const long long B   = in_sizes[1] / (A * 4);
    const long long C   = in_sizes[2] / (B * A);
    const long long BAC = B * A * C;
    const long long total = B * A;

    float* out = (float*)d_out;
    float* out_box  = out;                                        // BAC*6
    float* out_mask = (out_size >= (long long)(BAC * 7)) ? out + BAC * 6 : nullptr;
    float* out_bidx = (out_size >= (long long)(BAC * 8)) ? out + BAC * 7 : nullptr;

    // Hedge: if the harness allocated more than we write, clear the tail
    // (d_out is poisoned to 0xAA). Graph-capturable async memset.
    long long written = BAC * 6;
    if (out_mask) written = BAC * 7;
    if (out_bidx) written = BAC * 8;
    if ((long long)out_size > written) {
        cudaMemsetAsync(out + written, 0,
                        ((long long)out_size - written) * sizeof(float));
    }

    if (C == 8) {
        const long long blocks = (total + TPB - 1) / TPB;
        box_decode_c8_kernel<<<(unsigned)blocks, TPB>>>(
            anchors, loc, cls, varx_p, vary_p, thr_p,
            out_box, out_mask, out_bidx, (int)A, total);
    } else {
        const int threads = 256;
        const long long blocks = (total + threads - 1) / threads;
        box_decode_generic_kernel<<<(unsigned)blocks, threads>>>(
            anchors, loc, cls, varx_p, vary_p, thr_p,
            out_box, out_mask, out_bidx, (int)A, (int)C, total);
    }
}